// round 1
// baseline (speedup 1.0000x reference)
#include <cuda_runtime.h>
#include <math.h>

#define EMB 256
#define NH1 32
#define NH2 16
#define MAXDAGS 1024
#define MAXOPS  102400
#define PREDB 8

// ---------------- scratch (device globals; no allocation allowed) ----------------
__device__ int   g_offsets[MAXDAGS + 1];
__device__ int   g_dagid[MAXOPS];
__device__ float g_yzop[MAXDAGS * NH1];
__device__ float g_prpre[MAXDAGS * NH1];
__device__ float g_zop[NH1];
__device__ float g_zpr[NH1];
__device__ float g_partial[1024];
__device__ float g_inv;

// ---------------- prefix sum of num_ops -> op start offsets ----------------
__global__ void k_scan(const int* __restrict__ num_ops, int D) {
    __shared__ int s[1024];
    int t = threadIdx.x;
    int v = (t < D) ? num_ops[t] : 0;
    s[t] = v;
    __syncthreads();
    for (int off = 1; off < 1024; off <<= 1) {
        int u = (t >= off) ? s[t - off] : 0;
        __syncthreads();
        s[t] += u;
        __syncthreads();
    }
    g_offsets[t + 1] = s[t];
    if (t == 0) g_offsets[0] = 0;
}

// ---------------- fill per-op dag id (last dag pads the tail) ----------------
__global__ void k_fill(int N) {
    int d = blockIdx.x;
    int s = g_offsets[d];
    int e = g_offsets[d + 1];
    if ((int)blockIdx.x == (int)gridDim.x - 1) e = N;  // pad-with-last semantics
    if (e > N) e = N;
    if (s > N) s = N;
    for (int i = s + threadIdx.x; i < e; i += blockDim.x) g_dagid[i] = d;
}

// ---------------- z-part dots (dag independent), folds in b1 ----------------
__global__ void k_prez(const float* __restrict__ z,
                       const float* __restrict__ opW1, const float* __restrict__ opb1,
                       const float* __restrict__ prW1, const float* __restrict__ prb1) {
    __shared__ float sz[EMB];
    int t = threadIdx.x;
    for (int i = t; i < EMB; i += 64) sz[i] = z[i];
    __syncthreads();
    int j = t & 31;
    const float* W = (t < 32) ? (opW1 + 2 * EMB * NH1) : (prW1 + (1 + EMB) * NH1);
    float a0 = 0.f, a1 = 0.f, a2 = 0.f, a3 = 0.f;
    for (int k = 0; k < EMB; k += 4) {
        a0 += sz[k + 0] * W[(k + 0) * NH1 + j];
        a1 += sz[k + 1] * W[(k + 1) * NH1 + j];
        a2 += sz[k + 2] * W[(k + 2) * NH1 + j];
        a3 += sz[k + 3] * W[(k + 3) * NH1 + j];
    }
    float a = (a0 + a1) + (a2 + a3);
    if (t < 32) g_zop[j] = a + opb1[j];
    else        g_zpr[j] = a + prb1[j];
}

// ---------------- per-dag y-part dots for both branches ----------------
__global__ void __launch_bounds__(512) k_pre(
    const float* __restrict__ y,
    const float* __restrict__ opW1, const float* __restrict__ prW1, int D)
{
    __shared__ float sy[PREDB * EMB];   // 8 KB
    __shared__ float swo[64 * NH1];     // 8 KB
    __shared__ float swp[64 * NH1];     // 8 KB
    int t = threadIdx.x;
    int j = t & 31;
    int half = (t >> 5) & 1;
    int dl = t >> 6;
    int d = blockIdx.x * PREDB + dl;

    for (int idx = t; idx < PREDB * EMB; idx += 512) {
        int dd = blockIdx.x * PREDB + (idx >> 8);
        sy[idx] = (dd < D) ? y[(size_t)dd * EMB + (idx & 255)] : 0.f;
    }

    float a0 = 0.f, a1 = 0.f;
    for (int kc = 0; kc < EMB; kc += 64) {
        __syncthreads();
        for (int idx = t; idx < 64 * NH1; idx += 512) {
            swo[idx] = opW1[EMB * NH1 + kc * NH1 + idx];
            swp[idx] = prW1[NH1 + kc * NH1 + idx];
        }
        __syncthreads();
        const float* sw = half ? swp : swo;
        const float* yrow = sy + dl * EMB + kc;
#pragma unroll
        for (int k = 0; k < 64; k += 2) {
            a0 += yrow[k + 0] * sw[(k + 0) * NH1 + j];
            a1 += yrow[k + 1] * sw[(k + 1) * NH1 + j];
        }
    }
    if (d < D) {
        float a = a0 + a1;
        if (half == 0) g_yzop[d * NH1 + j]  = a + g_zop[j];
        else           g_prpre[d * NH1 + j] = a + g_zpr[j];
    }
}

// ---------------- main op GEMM + MLP tail + exp, block partial sums ----------------
#define BM 128
#define KC 32

__global__ void __launch_bounds__(128) k_ops(
    const float* __restrict__ x,  const float* __restrict__ W1,
    const float* __restrict__ W2, const float* __restrict__ b2,
    const float* __restrict__ W3, const float* __restrict__ b3,
    const float* __restrict__ msk, float* __restrict__ out, int N)
{
    __shared__ float sx[BM * (KC + 1)];   // 16.9 KB  [m][k]
    __shared__ float swc[KC * NH1];       // 4 KB     [k][j]
    __shared__ float sh[BM * (NH1 + 1)];  // 16.9 KB  staged h1-pre
    __shared__ float sw2[NH1 * NH2];
    __shared__ float sb2[NH2], sw3[NH2];
    __shared__ float sb3v;
    __shared__ float swr[4];

    int tid = threadIdx.x;
    int bm = blockIdx.x * BM;

    if (tid < 16) { sb2[tid] = b2[tid]; sw3[tid] = W3[tid]; }
    if (tid == 16) sb3v = b3[0];
    for (int i = tid; i < NH1 * NH2; i += 128) sw2[i] = W2[i];

    int n0 = (tid & 3) * 8;
    int m0 = (tid >> 2) * 4;

    float acc[4][8];
#pragma unroll
    for (int i = 0; i < 4; i++)
#pragma unroll
        for (int j = 0; j < 8; j++) acc[i][j] = 0.f;

    for (int kc = 0; kc < EMB; kc += KC) {
        __syncthreads();
        // stage x tile [128][32]  (coalesced LDG, conflict-free STS)
#pragma unroll
        for (int it = 0; it < 32; it++) {
            int idx = it * 128 + tid;
            int m = idx >> 5, k = idx & 31;
            int n = bm + m;
            sx[m * (KC + 1) + k] = (n < N) ? x[(size_t)n * EMB + kc + k] : 0.f;
        }
        // stage W1 chunk (rows kc..kc+31 are the x-part, contiguous)
#pragma unroll
        for (int it = 0; it < 8; it++) {
            int idx = it * 128 + tid;
            swc[idx] = W1[kc * NH1 + idx];
        }
        __syncthreads();
#pragma unroll
        for (int k = 0; k < KC; k++) {
            float xv[4], wv[8];
#pragma unroll
            for (int i = 0; i < 4; i++) xv[i] = sx[(m0 + i) * (KC + 1) + k];
#pragma unroll
            for (int j = 0; j < 8; j++) wv[j] = swc[k * NH1 + n0 + j];
#pragma unroll
            for (int i = 0; i < 4; i++)
#pragma unroll
                for (int j = 0; j < 8; j++) acc[i][j] += xv[i] * wv[j];
        }
    }
    __syncthreads();
#pragma unroll
    for (int i = 0; i < 4; i++)
#pragma unroll
        for (int j = 0; j < 8; j++) sh[(m0 + i) * (NH1 + 1) + n0 + j] = acc[i][j];
    __syncthreads();

    int n = bm + tid;
    float e = 0.f;
    if (n < N) {
        int dag = g_dagid[n];
        const float* yz = g_yzop + dag * NH1;
        float h1[NH1];
#pragma unroll
        for (int j = 0; j < NH1; j++)
            h1[j] = fmaxf(sh[tid * (NH1 + 1) + j] + yz[j], 0.f);
        float logit = sb3v;
#pragma unroll
        for (int i = 0; i < NH2; i++) {
            float a = sb2[i];
#pragma unroll
            for (int j = 0; j < NH1; j++) a += h1[j] * sw2[j * NH2 + i];
            logit += fmaxf(a, 0.f) * sw3[i];
        }
        logit -= (1.f - msk[n]) * 1000.f;
        e = expf(logit);          // no max-sub needed: logits O(1), masked underflow to 0
        out[n] = e;
    }
    // deterministic block partial sum
#pragma unroll
    for (int off = 16; off; off >>= 1) e += __shfl_down_sync(0xffffffffu, e, off);
    if ((tid & 31) == 0) swr[tid >> 5] = e;
    __syncthreads();
    if (tid == 0) g_partial[blockIdx.x] = (swr[0] + swr[1]) + (swr[2] + swr[3]);
}

// ---------------- deterministic final sum ----------------
__global__ void k_sum(int nb) {
    __shared__ float s[256];
    int t = threadIdx.x;
    float a = 0.f;
    for (int i = t; i < nb; i += 256) a += g_partial[i];
    s[t] = a;
    __syncthreads();
    for (int off = 128; off; off >>= 1) {
        if (t < off) s[t] += s[t + off];
        __syncthreads();
    }
    if (t == 0) g_inv = 1.0f / s[0];
}

__global__ void k_norm(float* __restrict__ out, int N) {
    int n = blockIdx.x * 256 + threadIdx.x;
    if (n < N) out[n] *= g_inv;
}

// ---------------- prlvl branch: per-dag MLP + softmax over workers ----------------
__global__ void __launch_bounds__(64) k_pr(
    const float* __restrict__ prW1, const float* __restrict__ prW2,
    const float* __restrict__ prb2, const float* __restrict__ prW3,
    const float* __restrict__ prb3, const float* __restrict__ msk,
    float* __restrict__ outp, int W)
{
    __shared__ float spre[NH1], sr0[NH1], sW2[NH1 * NH2], sb2[NH2], sW3[NH2];
    __shared__ float sb3v;
    __shared__ float sred[2];
    int d = blockIdx.x;
    int t = threadIdx.x;
    if (t < 32) { spre[t] = g_prpre[d * NH1 + t]; sr0[t] = prW1[t]; }
    for (int i = t; i < NH1 * NH2; i += 64) sW2[i] = prW2[i];
    if (t < 16) { sb2[t] = prb2[t]; sW3[t] = prW3[t]; }
    if (t == 16) sb3v = prb3[0];
    __syncthreads();

    float l = -1e30f;
    if (t < W) {
        float lim = (float)(t + 1);
        float h1[NH1];
#pragma unroll
        for (int j = 0; j < NH1; j++) h1[j] = fmaxf(spre[j] + lim * sr0[j], 0.f);
        float logit = sb3v;
#pragma unroll
        for (int i = 0; i < NH2; i++) {
            float a = sb2[i];
#pragma unroll
            for (int j = 0; j < NH1; j++) a += h1[j] * sW2[j * NH2 + i];
            logit += fmaxf(a, 0.f) * sW3[i];
        }
        l = logit - (1.f - msk[(size_t)d * W + t]) * 1000.f;
    }
    float m = l;
#pragma unroll
    for (int off = 16; off; off >>= 1) m = fmaxf(m, __shfl_xor_sync(0xffffffffu, m, off));
    if ((t & 31) == 0) sred[t >> 5] = m;
    __syncthreads();
    m = fmaxf(sred[0], sred[1]);
    float e = (t < W) ? expf(l - m) : 0.f;
    float s = e;
#pragma unroll
    for (int off = 16; off; off >>= 1) s += __shfl_xor_sync(0xffffffffu, s, off);
    __syncthreads();
    if ((t & 31) == 0) sred[t >> 5] = s;
    __syncthreads();
    s = sred[0] + sred[1];
    if (t < W) outp[(size_t)d * W + t] = e / s;
}

// ---------------- launch ----------------
extern "C" void kernel_launch(void* const* d_in, const int* in_sizes, int n_in,
                              void* d_out, int out_size) {
    // x is the largest input; everything after it is in fixed dict order.
    int ix = 0; long long best = -1;
    for (int i = 0; i < n_in; i++) {
        if ((long long)in_sizes[i] > best) { best = in_sizes[i]; ix = i; }
    }
    const int*   num_ops = (const int*)d_in[0];
    const float* x    = (const float*)d_in[ix];
    const float* y    = (const float*)d_in[ix + 1];
    const float* z    = (const float*)d_in[ix + 2];
    const float* omsk = (const float*)d_in[ix + 3];
    const float* pmsk = (const float*)d_in[ix + 4];
    const float* oW1  = (const float*)d_in[ix + 5];
    const float* ob1  = (const float*)d_in[ix + 6];
    const float* oW2  = (const float*)d_in[ix + 7];
    const float* ob2  = (const float*)d_in[ix + 8];
    const float* oW3  = (const float*)d_in[ix + 9];
    const float* ob3  = (const float*)d_in[ix + 10];
    const float* pW1  = (const float*)d_in[ix + 11];
    const float* pb1  = (const float*)d_in[ix + 12];
    const float* pW2  = (const float*)d_in[ix + 13];
    const float* pb2  = (const float*)d_in[ix + 14];
    const float* pW3  = (const float*)d_in[ix + 15];
    const float* pb3  = (const float*)d_in[ix + 16];

    int N = in_sizes[ix] / EMB;
    int D = in_sizes[ix + 1] / EMB;
    int W = in_sizes[ix + 4] / D;

    float* out  = (float*)d_out;
    float* outp = out + N;

    k_scan<<<1, 1024>>>(num_ops, D);
    k_fill<<<D, 128>>>(N);
    k_prez<<<1, 64>>>(z, oW1, ob1, pW1, pb1);
    k_pre<<<(D + PREDB - 1) / PREDB, 512>>>(y, oW1, pW1, D);
    int nb = (N + BM - 1) / BM;
    k_ops<<<nb, 128>>>(x, oW1, oW2, ob2, oW3, ob3, omsk, out, N);
    k_sum<<<1, 256>>>(nb);
    k_norm<<<(N + 255) / 256, 256>>>(out, N);
    k_pr<<<D, 64>>>(pW1, pW2, pb2, pW3, pb3, pmsk, outp, W);
}

// round 2
// speedup vs baseline: 1.2122x; 1.2122x over previous
#include <cuda_runtime.h>
#include <math.h>

#define EMB 256
#define NH1 32
#define NH2 16
#define MAXDAGS 1024
#define MAXOPS  102400

// ---------------- scratch (device globals; no allocation allowed) ----------------
__device__ int   g_offsets[MAXDAGS + 1];
__device__ int   g_dagid[MAXOPS];
__device__ float g_yzop[MAXDAGS * NH1];
__device__ float g_prpre[MAXDAGS * NH1];
__device__ float g_zop[NH1];
__device__ float g_zpr[NH1];
__device__ float g_partial[1024];
__device__ float g_inv;
__device__ unsigned int g_counter;

// ---------------- f32x2 helpers (sm_100+ packed FMA) ----------------
__device__ __forceinline__ void ffma2(unsigned long long& d, unsigned long long a, unsigned long long b) {
    asm("fma.rn.f32x2 %0, %1, %2, %0;" : "+l"(d) : "l"(a), "l"(b));
}
__device__ __forceinline__ unsigned long long pack2(float x, float y) {
    unsigned long long r;
    asm("mov.b64 %0, {%1,%2};" : "=l"(r) : "f"(x), "f"(y));
    return r;
}
__device__ __forceinline__ float2 unpack2(unsigned long long v) {
    float2 r;
    asm("mov.b64 {%0,%1}, %2;" : "=f"(r.x), "=f"(r.y) : "l"(v));
    return r;
}

// ================= kernel A: block0 = prefix scan (+counter reset), block1 = z-dots =================
__global__ void __launch_bounds__(1024) k_A(
    const int* __restrict__ num_ops, const float* __restrict__ z,
    const float* __restrict__ opW1, const float* __restrict__ opb1,
    const float* __restrict__ prW1, const float* __restrict__ prb1, int D)
{
    __shared__ int s[1024];
    __shared__ float sz[EMB];
    int t = threadIdx.x;
    if (blockIdx.x == 0) {
        if (t == 0) g_counter = 0u;
        int v = (t < D) ? num_ops[t] : 0;
        s[t] = v;
        __syncthreads();
        for (int off = 1; off < 1024; off <<= 1) {
            int u = (t >= off) ? s[t - off] : 0;
            __syncthreads();
            s[t] += u;
            __syncthreads();
        }
        g_offsets[t + 1] = s[t];
        if (t == 0) g_offsets[0] = 0;
    } else {
        for (int i = t; i < EMB; i += 1024) sz[i] = z[i];
        __syncthreads();
        if (t < 64) {
            int j = t & 31;
            const float* W = (t < 32) ? (opW1 + 2 * EMB * NH1) : (prW1 + (1 + EMB) * NH1);
            float a0 = 0.f, a1 = 0.f, a2 = 0.f, a3 = 0.f;
            for (int k = 0; k < EMB; k += 4) {
                a0 += sz[k + 0] * W[(k + 0) * NH1 + j];
                a1 += sz[k + 1] * W[(k + 1) * NH1 + j];
                a2 += sz[k + 2] * W[(k + 2) * NH1 + j];
                a3 += sz[k + 3] * W[(k + 3) * NH1 + j];
            }
            float a = (a0 + a1) + (a2 + a3);
            if (t < 32) g_zop[j] = a + opb1[j];
            else        g_zpr[j] = a + prb1[j];
        }
    }
}

// ================= kernel B: blocks [0,D) = fill dag ids, rest = per-dag y-dots =================
__global__ void __launch_bounds__(512) k_B(
    const float* __restrict__ y,
    const float* __restrict__ opW1, const float* __restrict__ prW1,
    int D, int N, int nb16)
{
    __shared__ float sy[16 * EMB];   // 16 KB
    __shared__ float sw[64 * NH1];   // 8 KB
    int t = threadIdx.x;
    if ((int)blockIdx.x < D) {
        int d = blockIdx.x;
        int s = g_offsets[d];
        int e = g_offsets[d + 1];
        if (d == D - 1) e = N;                 // pad-with-last semantics
        if (e > N) e = N;
        if (s > N) s = N;
        for (int i = s + t; i < e; i += 512) g_dagid[i] = d;
        return;
    }
    int bp = blockIdx.x - D;
    int branch = (bp >= nb16) ? 1 : 0;
    int chunk = branch ? bp - nb16 : bp;
    int w = t >> 5, j = t & 31;
    int d = chunk * 16 + w;

    for (int idx = t; idx < 16 * EMB; idx += 512) {
        int dd = chunk * 16 + (idx >> 8);
        sy[idx] = (dd < D) ? y[(size_t)dd * EMB + (idx & 255)] : 0.f;
    }
    const float* Wm = branch ? (prW1 + NH1) : (opW1 + EMB * NH1);
    float a0 = 0.f, a1 = 0.f;
    for (int kc = 0; kc < EMB; kc += 64) {
        __syncthreads();
        for (int idx = t; idx < 64 * NH1; idx += 512) sw[idx] = Wm[(size_t)kc * NH1 + idx];
        __syncthreads();
        const float* yr = sy + w * EMB + kc;
#pragma unroll
        for (int k = 0; k < 64; k += 2) {
            a0 += yr[k + 0] * sw[(k + 0) * NH1 + j];
            a1 += yr[k + 1] * sw[(k + 1) * NH1 + j];
        }
    }
    if (d < D) {
        float a = a0 + a1;
        if (!branch) g_yzop[d * NH1 + j]  = a + g_zop[j];
        else         g_prpre[d * NH1 + j] = a + g_zpr[j];
    }
}

// ================= kernel C: main GEMM (f32x2) + MLP tail + exp + global sum =================
#define BM 256
#define KC 16
#define SXP 260   // sxT row stride (floats)
#define SHP 34    // sh row stride (floats, even for u64 stores)

__global__ void __launch_bounds__(128) k_ops(
    const float* __restrict__ x,  const float* __restrict__ W1,
    const float* __restrict__ W2, const float* __restrict__ b2,
    const float* __restrict__ W3, const float* __restrict__ b3,
    const float* __restrict__ msk, float* __restrict__ out, int N)
{
    __shared__ float s_buf[BM * SHP];      // union: sxT [KC][260] then sh [256][34]
    __shared__ float swc[KC * NH1];        // W1 chunk [k][j]
    __shared__ float sw2[NH1 * NH2];
    __shared__ float sb2[NH2], sw3[NH2];
    __shared__ float sb3v;
    __shared__ float swr[4];
    __shared__ int   s_last;

    int tid = threadIdx.x;
    int bm = blockIdx.x * BM;

    if (tid < 16) { sb2[tid] = b2[tid]; sw3[tid] = W3[tid]; }
    if (tid == 16) sb3v = b3[0];
    for (int i = tid; i < NH1 * NH2; i += 128) sw2[i] = W2[i];

    int j0 = (tid >> 5) * 8;     // warp -> j group (w broadcast within warp)
    int m0 = (tid & 31) * 8;     // lane -> 8 rows

    unsigned long long acc[8][4];
#pragma unroll
    for (int i = 0; i < 8; i++)
#pragma unroll
        for (int p = 0; p < 4; p++) acc[i][p] = 0ull;

    for (int kc = 0; kc < EMB; kc += KC) {
        __syncthreads();
        // stage x tile transposed: sxT[k][m], coalesced float4 global loads
#pragma unroll
        for (int it = 0; it < 8; it++) {
            int fi = it * 128 + tid;
            int row = fi >> 2, kq = fi & 3;
            int n = bm + row;
            float4 v = make_float4(0.f, 0.f, 0.f, 0.f);
            if (n < N) v = *reinterpret_cast<const float4*>(&x[(size_t)n * EMB + kc + kq * 4]);
            s_buf[(kq * 4 + 0) * SXP + row] = v.x;
            s_buf[(kq * 4 + 1) * SXP + row] = v.y;
            s_buf[(kq * 4 + 2) * SXP + row] = v.z;
            s_buf[(kq * 4 + 3) * SXP + row] = v.w;
        }
#pragma unroll
        for (int it = 0; it < 4; it++) {
            int idx = it * 128 + tid;
            swc[idx] = W1[(size_t)kc * NH1 + idx];
        }
        __syncthreads();
#pragma unroll
        for (int k = 0; k < KC; k++) {
            const float4* xp = reinterpret_cast<const float4*>(&s_buf[k * SXP + m0]);
            float4 xa = xp[0], xb = xp[1];
            const ulonglong2* wp = reinterpret_cast<const ulonglong2*>(&swc[k * NH1 + j0]);
            ulonglong2 wA = wp[0], wB = wp[1];   // broadcast within warp
            float xs[8] = {xa.x, xa.y, xa.z, xa.w, xb.x, xb.y, xb.z, xb.w};
#pragma unroll
            for (int i = 0; i < 8; i++) {
                unsigned long long xd = pack2(xs[i], xs[i]);
                ffma2(acc[i][0], xd, wA.x);
                ffma2(acc[i][1], xd, wA.y);
                ffma2(acc[i][2], xd, wB.x);
                ffma2(acc[i][3], xd, wB.y);
            }
        }
    }
    __syncthreads();
    // stage h1-pre to smem (u64 stores, aligned)
#pragma unroll
    for (int i = 0; i < 8; i++)
#pragma unroll
        for (int p = 0; p < 4; p++)
            *reinterpret_cast<unsigned long long*>(&s_buf[(m0 + i) * SHP + j0 + 2 * p]) = acc[i][p];
    __syncthreads();

    // ---- tail: 2 rows per thread ----
    const unsigned long long* w2_64 = reinterpret_cast<const unsigned long long*>(sw2);
    float bsum = 0.f;
#pragma unroll
    for (int rr = 0; rr < 2; rr++) {
        int r = tid + rr * 128;
        int n = bm + r;
        if (n < N) {
            int dag = g_dagid[n];
            const float4* yz4 = reinterpret_cast<const float4*>(&g_yzop[dag * NH1]);
            float h1[NH1];
#pragma unroll
            for (int q = 0; q < 8; q++) {
                float4 v = yz4[q];
                h1[q * 4 + 0] = fmaxf(s_buf[r * SHP + q * 4 + 0] + v.x, 0.f);
                h1[q * 4 + 1] = fmaxf(s_buf[r * SHP + q * 4 + 1] + v.y, 0.f);
                h1[q * 4 + 2] = fmaxf(s_buf[r * SHP + q * 4 + 2] + v.z, 0.f);
                h1[q * 4 + 3] = fmaxf(s_buf[r * SHP + q * 4 + 3] + v.w, 0.f);
            }
            unsigned long long a2[8];
#pragma unroll
            for (int p = 0; p < 8; p++) a2[p] = pack2(sb2[2 * p], sb2[2 * p + 1]);
#pragma unroll
            for (int j = 0; j < NH1; j++) {
                unsigned long long hd = pack2(h1[j], h1[j]);
#pragma unroll
                for (int p = 0; p < 8; p++) ffma2(a2[p], hd, w2_64[j * 8 + p]);
            }
            float logit = sb3v;
#pragma unroll
            for (int p = 0; p < 8; p++) {
                float2 f = unpack2(a2[p]);
                logit += fmaxf(f.x, 0.f) * sw3[2 * p] + fmaxf(f.y, 0.f) * sw3[2 * p + 1];
            }
            logit -= (1.f - msk[n]) * 1000.f;
            float e = expf(logit);   // logits O(1); masked -> exp(-1000)=0. no max-sub needed
            out[n] = e;
            bsum += e;
        }
    }
    // deterministic block partial sum
#pragma unroll
    for (int off = 16; off; off >>= 1) bsum += __shfl_down_sync(0xffffffffu, bsum, off);
    if ((tid & 31) == 0) swr[tid >> 5] = bsum;
    __syncthreads();
    if (tid == 0) {
        g_partial[blockIdx.x] = (swr[0] + swr[1]) + (swr[2] + swr[3]);
        __threadfence();
        unsigned int prev = atomicAdd(&g_counter, 1u);
        s_last = (prev == gridDim.x - 1) ? 1 : 0;
    }
    __syncthreads();
    if (s_last) {
        __threadfence();
        const volatile float* vp = g_partial;
        float a = 0.f;
        for (int i = tid; i < (int)gridDim.x; i += 128) a += vp[i];
#pragma unroll
        for (int off = 16; off; off >>= 1) a += __shfl_down_sync(0xffffffffu, a, off);
        if ((tid & 31) == 0) swr[tid >> 5] = a;
        __syncthreads();
        if (tid == 0) g_inv = 1.0f / ((swr[0] + swr[1]) + (swr[2] + swr[3]));
    }
}

// ================= kernel E: blocks [0,nbN) normalize ops, rest = prlvl branch =================
__global__ void __launch_bounds__(256) k_E(
    const float* __restrict__ prW1, const float* __restrict__ prW2,
    const float* __restrict__ prb2, const float* __restrict__ prW3,
    const float* __restrict__ prb3, const float* __restrict__ pmsk,
    float* __restrict__ out, float* __restrict__ outp, int N, int W, int nbN)
{
    int t = threadIdx.x;
    if ((int)blockIdx.x < nbN) {
        float inv = g_inv;
        int i4 = blockIdx.x * 256 + t;
        if (i4 * 4 < N) {
            float4* o4 = reinterpret_cast<float4*>(out);
            float4 v = o4[i4];
            v.x *= inv; v.y *= inv; v.z *= inv; v.w *= inv;
            o4[i4] = v;
        }
        return;
    }
    __shared__ float spre[NH1], sr0[NH1], sW2[NH1 * NH2], sb2[NH2], sW3[NH2];
    __shared__ float sb3v;
    __shared__ float sred[2];
    int d = blockIdx.x - nbN;
    if (t < 32) { spre[t] = g_prpre[d * NH1 + t]; sr0[t] = prW1[t]; }
    for (int i = t; i < NH1 * NH2; i += 256) sW2[i] = prW2[i];
    if (t < 16) { sb2[t] = prb2[t]; sW3[t] = prW3[t]; }
    if (t == 16) sb3v = prb3[0];
    __syncthreads();

    float l = -1e30f;
    if (t < W) {
        float lim = (float)(t + 1);
        float h1[NH1];
#pragma unroll
        for (int j = 0; j < NH1; j++) h1[j] = fmaxf(spre[j] + lim * sr0[j], 0.f);
        float logit = sb3v;
#pragma unroll
        for (int i = 0; i < NH2; i++) {
            float a = sb2[i];
#pragma unroll
            for (int j = 0; j < NH1; j++) a += h1[j] * sW2[j * NH2 + i];
            logit += fmaxf(a, 0.f) * sW3[i];
        }
        l = logit - (1.f - pmsk[(size_t)d * W + t]) * 1000.f;
    }
    if (t < 64) {
        float m = l;
#pragma unroll
        for (int off = 16; off; off >>= 1) m = fmaxf(m, __shfl_xor_sync(0xffffffffu, m, off));
        if ((t & 31) == 0) sred[t >> 5] = m;
    }
    __syncthreads();
    float mm = fmaxf(sred[0], sred[1]);
    float e = (t < W) ? expf(l - mm) : 0.f;
    __syncthreads();
    if (t < 64) {
        float s = e;
#pragma unroll
        for (int off = 16; off; off >>= 1) s += __shfl_xor_sync(0xffffffffu, s, off);
        if ((t & 31) == 0) sred[t >> 5] = s;
    }
    __syncthreads();
    float ss = sred[0] + sred[1];
    if (t < W) outp[(size_t)d * W + t] = e / ss;
}

// ================= launch =================
extern "C" void kernel_launch(void* const* d_in, const int* in_sizes, int n_in,
                              void* d_out, int out_size) {
    int ix = 0; long long best = -1;
    for (int i = 0; i < n_in; i++)
        if ((long long)in_sizes[i] > best) { best = in_sizes[i]; ix = i; }

    const int*   num_ops = (const int*)d_in[0];
    const float* x    = (const float*)d_in[ix];
    const float* y    = (const float*)d_in[ix + 1];
    const float* z    = (const float*)d_in[ix + 2];
    const float* omsk = (const float*)d_in[ix + 3];
    const float* pmsk = (const float*)d_in[ix + 4];
    const float* oW1  = (const float*)d_in[ix + 5];
    const float* ob1  = (const float*)d_in[ix + 6];
    const float* oW2  = (const float*)d_in[ix + 7];
    const float* ob2  = (const float*)d_in[ix + 8];
    const float* oW3  = (const float*)d_in[ix + 9];
    const float* ob3  = (const float*)d_in[ix + 10];
    const float* pW1  = (const float*)d_in[ix + 11];
    const float* pW2  = (const float*)d_in[ix + 13];
    const float* pb2  = (const float*)d_in[ix + 14];
    const float* pW3  = (const float*)d_in[ix + 15];
    const float* pb3  = (const float*)d_in[ix + 16];
    const float* pb1  = (const float*)d_in[ix + 12];

    int N = in_sizes[ix] / EMB;
    int D = in_sizes[ix + 1] / EMB;
    int W = in_sizes[ix + 4] / D;

    float* out  = (float*)d_out;
    float* outp = out + N;

    int nb16 = (D + 15) / 16;
    int nb   = (N + BM - 1) / BM;
    int nbN  = (N + 1023) / 1024;

    k_A<<<2, 1024>>>(num_ops, z, oW1, ob1, pW1, pb1, D);
    k_B<<<D + 2 * nb16, 512>>>(y, oW1, pW1, D, N, nb16);
    k_ops<<<nb, 128>>>(x, oW1, oW2, ob2, oW3, ob3, omsk, out, N);
    k_E<<<nbN + D, 256>>>(pW1, pW2, pb2, pW3, pb3, pmsk, out, outp, N, W, nbN);
}